// round 14
// baseline (speedup 1.0000x reference)
#include <cuda_runtime.h>
#include <cuda_bf16.h>
#include <stdint.h>

#define NUM_NODES 10000
#define NUM_EDGES 640000
#define GNN_IN    128
#define HID       256
#define NBLK      592          // 148 SMs x 4 resident blocks -- all wave-1
#define N_ITEMS   1256         // 157 m-tiles(64) x 8 n-tiles(64)

// Per-node tables: PAB[node][0:256]  = x[node]@W1[0:128] + b1  (b1 folded)
//                  PAB[node][256:512] = x[node]@W1[128:256]
__device__ __align__(16) __nv_bfloat16 g_pab[NUM_NODES * 512];

// Epoch grid-barrier counter: grows by exactly NBLK per launch, never reset.
__device__ unsigned g_bar;

// ---------------------------------------------------------------------------
// Helpers
// ---------------------------------------------------------------------------
__device__ __forceinline__ unsigned long long pack_f32x2(float lo, float hi) {
    unsigned long long r;
    asm("mov.b64 %0, {%1, %2};" : "=l"(r) : "f"(lo), "f"(hi));
    return r;
}
__device__ __forceinline__ uint32_t f32_to_tf32(float f) {
    uint32_t r;
    asm("cvt.rna.tf32.f32 %0, %1;" : "=r"(r) : "f"(f));
    return r;
}
// Pack two fp32 -> bf16x2 (lo in lower half, hi in upper half).
__device__ __forceinline__ uint32_t bf16x2_pack(float lo, float hi) {
    uint32_t r;
    asm("cvt.rn.bf16x2.f32 %0, %1, %2;" : "=r"(r) : "f"(hi), "f"(lo));
    return r;
}
// Broadcast one fp32 into both bf16 halves.
__device__ __forceinline__ uint32_t bf16x2_bcast(float v) {
    uint32_t r;
    asm("cvt.rn.bf16x2.f32 %0, %1, %1;" : "=r"(r) : "f"(v));
    return r;
}
__device__ __forceinline__ __nv_bfloat162 asb2(uint32_t u) {
    return *reinterpret_cast<__nv_bfloat162*>(&u);
}
__device__ __forceinline__ uint32_t asu32(__nv_bfloat162 v) {
    return *reinterpret_cast<uint32_t*>(&v);
}
__device__ __forceinline__ void dist_to_bf16x2(float4 d, uint32_t* r) {
    r[0] = bf16x2_bcast(d.x);
    r[1] = bf16x2_bcast(d.y);
    r[2] = bf16x2_bcast(d.z);
    r[3] = bf16x2_bcast(d.w);
}

__device__ __forceinline__ uint4 gatherA(int node, int j0) {
    return *(const uint4*)(g_pab + (size_t)node * 512 + j0);
}
__device__ __forceinline__ uint4 gatherB(int node, int j0) {
    return *(const uint4*)(g_pab + (size_t)node * 512 + 256 + j0);
}

// Hidden layer fully in packed bf16: HADD2 + 4xHFMA2 + HMAX2 per unit-pair,
// then fp32 w2-dot. Saves ~12 instrs/edge and 16 live regs vs the f32x2 path.
__device__ __forceinline__ float edge_mlp(
    uint4 pa, uint4 pb, const uint32_t dd[4],
    const uint32_t wcb[4][4], const float w2r[8])
{
    const unsigned* A = (const unsigned*)&pa;
    const unsigned* B = (const unsigned*)&pb;
    const __nv_bfloat162 zero2 = asb2(0u);
    float accL = 0.f, accH = 0.f;
#pragma unroll
    for (int p = 0; p < 4; p++) {
        __nv_bfloat162 t = __hadd2(asb2(A[p]), asb2(B[p]));
        t = __hfma2(asb2(dd[0]), asb2(wcb[0][p]), t);
        t = __hfma2(asb2(dd[1]), asb2(wcb[1][p]), t);
        t = __hfma2(asb2(dd[2]), asb2(wcb[2][p]), t);
        t = __hfma2(asb2(dd[3]), asb2(wcb[3][p]), t);
        t = __hmax2(t, zero2);
        unsigned w = asu32(t);
        float lo = __uint_as_float(w << 16);
        float hi = __uint_as_float(w & 0xffff0000u);
        accL = fmaf(lo, w2r[2 * p], accL);
        accH = fmaf(hi, w2r[2 * p + 1], accH);
    }
    return accL + accH;
}

__device__ __forceinline__ void reduce_store(
    float ra0, float ra1, int re, int lane, float bias2, float* out)
{
    float s0 = ra0 + __shfl_xor_sync(0xffffffffu, ra0, 16);
    float s1 = ra1 + __shfl_xor_sync(0xffffffffu, ra1, 16);
    float c  = (lane < 16) ? s0 : s1;
    c += __shfl_xor_sync(0xffffffffu, c, 8);
    c += __shfl_xor_sync(0xffffffffu, c, 4);
    c += __shfl_xor_sync(0xffffffffu, c, 2);
    c += __shfl_xor_sync(0xffffffffu, c, 1);
    if ((lane & 15) == 0) {
        float z = c + bias2;
        out[re + (lane >> 4)] = 1.f / (1.f + __expf(-z));
    }
}

// ---------------------------------------------------------------------------
// Fused persistent kernel: phase1 tf32-MMA precompute -> grid barrier ->
// phase2 edge MLP (deferred-reduction pipeline, bf16 hidden).
// ---------------------------------------------------------------------------
__global__ __launch_bounds__(128, 4) void fused_kernel(
    const float* __restrict__ x,
    const int*   __restrict__ edge_index,
    const float* __restrict__ edge_dist,
    const float* __restrict__ w1,
    const float* __restrict__ b1,
    const float* __restrict__ w2,
    const float* __restrict__ b2,
    float* __restrict__ out)
{
    __shared__ float Ws[128][68];   // 64-col W slice, pad 68: conflict-free LDS

    const int tid  = threadIdx.x;
    const int wid  = tid >> 5;      // 0..3
    const int lane = tid & 31;
    const int g    = lane >> 2;     // 0..7
    const int t    = lane & 3;      // 0..3

    // ===================== Phase 1: precompute GEMM =====================
    int prev_nt = -1;
    for (int item = blockIdx.x; item < N_ITEMS; item += NBLK) {
        const int nt = item & 7;
        const int mt = item >> 3;
        const int n0 = nt * 64;
        const int m0 = mt * 64 + wid * 16;

        const float* wbase = (n0 < 256) ? (w1 + n0)
                                        : (w1 + 128 * HID + (n0 - 256));
        if (nt != prev_nt) {
            if (prev_nt != -1) __syncthreads();
#pragma unroll
            for (int i = 0; i < 16; i++) {
                int idx4 = i * 128 + tid;
                int row  = idx4 >> 4;
                int c4   = idx4 & 15;
                float4 v = *(const float4*)(wbase + (size_t)row * HID + c4 * 4);
                *(float4*)&Ws[row][c4 * 4] = v;
            }
            __syncthreads();
            prev_nt = nt;
        }

        const int r0 = m0 + g, r1 = m0 + g + 8;
        const float* arow0 = x + (size_t)min(r0, NUM_NODES - 1) * GNN_IN;
        const float* arow1 = x + (size_t)min(r1, NUM_NODES - 1) * GNN_IN;

        float c[8][4];
#pragma unroll
        for (int nc = 0; nc < 8; nc++)
#pragma unroll
            for (int i = 0; i < 4; i++) c[nc][i] = 0.f;

#pragma unroll
        for (int ks = 0; ks < 16; ks++) {
            const int k0 = ks * 8;
            uint32_t a0 = f32_to_tf32(arow0[k0 + t]);
            uint32_t a1 = f32_to_tf32(arow1[k0 + t]);
            uint32_t a2 = f32_to_tf32(arow0[k0 + t + 4]);
            uint32_t a3 = f32_to_tf32(arow1[k0 + t + 4]);

#pragma unroll
            for (int nc = 0; nc < 8; nc++) {
                uint32_t b0  = f32_to_tf32(Ws[k0 + t][nc * 8 + g]);
                uint32_t b1v = f32_to_tf32(Ws[k0 + t + 4][nc * 8 + g]);
                asm("mma.sync.aligned.m16n8k8.row.col.f32.tf32.tf32.f32 "
                    "{%0,%1,%2,%3}, {%4,%5,%6,%7}, {%8,%9}, {%0,%1,%2,%3};"
                    : "+f"(c[nc][0]), "+f"(c[nc][1]), "+f"(c[nc][2]), "+f"(c[nc][3])
                    : "r"(a0), "r"(a1), "r"(a2), "r"(a3), "r"(b0), "r"(b1v));
            }
        }

#pragma unroll
        for (int nc = 0; nc < 8; nc++) {
            const int col = n0 + nc * 8 + 2 * t;
            float ba0 = 0.f, ba1 = 0.f;
            if (n0 < 256) { ba0 = b1[col]; ba1 = b1[col + 1]; }

            if (r0 < NUM_NODES) {
                __nv_bfloat162 p;
                p.x = __float2bfloat16_rn(c[nc][0] + ba0);
                p.y = __float2bfloat16_rn(c[nc][1] + ba1);
                *(__nv_bfloat162*)(g_pab + (size_t)r0 * 512 + col) = p;
            }
            if (r1 < NUM_NODES) {
                __nv_bfloat162 p;
                p.x = __float2bfloat16_rn(c[nc][2] + ba0);
                p.y = __float2bfloat16_rn(c[nc][3] + ba1);
                *(__nv_bfloat162*)(g_pab + (size_t)r1 * 512 + col) = p;
            }
        }
    }

    // === Edge-phase weight preload (independent of g_pab; hides in skew) ===
    const int j0 = lane * 8;
    uint32_t wcb[4][4];          // W1c rows as bf16x2 pairs (16 regs)
    float w2r[8];
#pragma unroll
    for (int i = 0; i < 8; i++) w2r[i] = w2[j0 + i];
#pragma unroll
    for (int r = 0; r < 4; r++)
#pragma unroll
        for (int p = 0; p < 4; p++)
            wcb[r][p] = bf16x2_pack(w1[(size_t)(256 + r) * HID + j0 + 2 * p],
                                    w1[(size_t)(256 + r) * HID + j0 + 2 * p + 1]);
    const float bias2 = b2[0];

    // ===================== Grid barrier (epoch ticket) =====================
    __syncthreads();
    if (tid == 0) {
        __threadfence();
        unsigned tkt = atomicAdd(&g_bar, 1u);
        unsigned target = (tkt / NBLK + 1u) * NBLK;
        unsigned v;
        do {
            asm volatile("ld.acquire.gpu.global.u32 %0, [%1];"
                         : "=r"(v) : "l"(&g_bar));
            if (v < target) __nanosleep(64);
        } while (v < target);
    }
    __syncthreads();

    // ===================== Phase 2: edge MLP =====================
    const int warp   = blockIdx.x * 4 + wid;
    const int nwarps = NBLK * 4;                       // 2368

    const int stride = nwarps * 2;
    int ec = warp * 2;
    if (ec >= NUM_EDGES) return;

    const int2*   idx2  = (const int2*)edge_index;
    const float4* dist4 = (const float4*)edge_dist;

    int en  = ec + stride;
    int enc = (en < NUM_EDGES - 2) ? en : (NUM_EDGES - 2);
    int2 ia = idx2[ec], ib = idx2[ec + 1];
    int2 ja = idx2[enc], jb = idx2[enc + 1];

    uint4 pa0 = gatherA(ia.x, j0), pb0 = gatherB(ia.y, j0);
    uint4 pa1 = gatherA(ib.x, j0), pb1 = gatherB(ib.y, j0);
    uint32_t dA0[4], dB0[4], dA1[4], dB1[4];
    dist_to_bf16x2(dist4[ec],     dA0);
    dist_to_bf16x2(dist4[ec + 1], dB0);

    uint4 qa0 = gatherA(ja.x, j0), qb0 = gatherB(ja.y, j0);
    uint4 qa1 = gatherA(jb.x, j0), qb1 = gatherB(jb.y, j0);
    dist_to_bf16x2(dist4[enc],     dA1);
    dist_to_bf16x2(dist4[enc + 1], dB1);

    int e2  = en + stride;
    int e2c = (e2 < NUM_EDGES - 2) ? e2 : (NUM_EDGES - 2);
    ja = idx2[e2c];  jb = idx2[e2c + 1];

    float ra0 = edge_mlp(pa0, pb0, dA0, wcb, w2r);
    float ra1 = edge_mlp(pa1, pb1, dB0, wcb, w2r);
    int   re  = ec;

    ec = en;
    if (ec >= NUM_EDGES) {
        reduce_store(ra0, ra1, re, lane, bias2, out);
        return;
    }
    en = e2;  enc = e2c;

    for (;;) {
        // ---- half A: gathers->set0(en); MLP from setQ(ec); reduce (re) ----
        pa0 = gatherA(ja.x, j0);  pb0 = gatherB(ja.y, j0);
        pa1 = gatherA(jb.x, j0);  pb1 = gatherB(jb.y, j0);
        dist_to_bf16x2(dist4[enc],     dA0);
        dist_to_bf16x2(dist4[enc + 1], dB0);
        {
            int e3  = en + stride;
            int e3c = (e3 < NUM_EDGES - 2) ? e3 : (NUM_EDGES - 2);
            ja = idx2[e3c];  jb = idx2[e3c + 1];

            float a0 = edge_mlp(qa0, qb0, dA1, wcb, w2r);
            float a1 = edge_mlp(qa1, qb1, dB1, wcb, w2r);
            reduce_store(ra0, ra1, re, lane, bias2, out);
            ra0 = a0;  ra1 = a1;  re = ec;

            ec = en;
            if (ec >= NUM_EDGES) break;
            en = e3;  enc = e3c;
        }

        // ---- half B: gathers->setQ(en); MLP from set0(ec); reduce (re) ----
        qa0 = gatherA(ja.x, j0);  qb0 = gatherB(ja.y, j0);
        qa1 = gatherA(jb.x, j0);  qb1 = gatherB(jb.y, j0);
        dist_to_bf16x2(dist4[enc],     dA1);
        dist_to_bf16x2(dist4[enc + 1], dB1);
        {
            int e3  = en + stride;
            int e3c = (e3 < NUM_EDGES - 2) ? e3 : (NUM_EDGES - 2);
            ja = idx2[e3c];  jb = idx2[e3c + 1];

            float a0 = edge_mlp(pa0, pb0, dA0, wcb, w2r);
            float a1 = edge_mlp(pa1, pb1, dB0, wcb, w2r);
            reduce_store(ra0, ra1, re, lane, bias2, out);
            ra0 = a0;  ra1 = a1;  re = ec;

            ec = en;
            if (ec >= NUM_EDGES) break;
            en = e3;  enc = e3c;
        }
    }

    reduce_store(ra0, ra1, re, lane, bias2, out);
}

// ---------------------------------------------------------------------------
extern "C" void kernel_launch(void* const* d_in, const int* in_sizes, int n_in,
                              void* d_out, int out_size) {
    const float* x          = (const float*)d_in[0];
    const int*   edge_index = (const int*)d_in[1];
    const float* edge_dist  = (const float*)d_in[2];
    const float* w1         = (const float*)d_in[3];
    const float* b1         = (const float*)d_in[4];
    const float* w2         = (const float*)d_in[5];
    const float* b2         = (const float*)d_in[6];
    float*       out        = (float*)d_out;

    fused_kernel<<<NBLK, 128>>>(x, edge_index, edge_dist, w1, b1, w2, b2, out);
}